// round 2
// baseline (speedup 1.0000x reference)
#include <cuda_runtime.h>
#include <cuda_bf16.h>
#include <cstdint>

// Problem constants (shapes are fixed by the dataset)
#define BB   512      // batch
#define TT   64       // encoder steps
#define CC   512      // encoder channels
#define HH   512      // hidden
#define NC   96       // classes
#define NS   26       // num decode steps (MAXLEN+1)

// ---------------- device scratch (allocation-free rule: __device__ globals) ----
__device__ float g_Hproj[(size_t)BB * TT * HH];   // 67 MB
__device__ float g_q   [(size_t)BB * HH];
__device__ float g_ctx [(size_t)BB * HH];
__device__ float g_z   [(size_t)BB * 4 * HH];
__device__ float g_h   [(size_t)BB * HH];
__device__ float g_c   [(size_t)BB * HH];
__device__ float g_hs  [(size_t)BB * NS * HH];    // 27 MB

// ---------------- generic fp32 tiled GEMM: C = A1@B1 (+ A2@B2) (+ bias) -------
// 128x128 block tile, BK=16, 256 threads, 8x8 per thread.
#define BM 128
#define BN 128
#define BK 16

__global__ __launch_bounds__(256)
void gemm_dual(const float* __restrict__ A1, const float* __restrict__ B1,
               const float* __restrict__ A2, const float* __restrict__ B2,
               const float* __restrict__ bias, float* __restrict__ C,
               int M, int N, int K, int lda, int ldb, int ldc)
{
    __shared__ float As[BK][BM];
    __shared__ float Bs[BK][BN];

    const int tid = threadIdx.x;
    const int m0 = blockIdx.y * BM;
    const int n0 = blockIdx.x * BN;
    const int tx = tid & 15;        // 0..15 -> N sub
    const int ty = tid >> 4;        // 0..15 -> M sub

    float acc[8][8];
#pragma unroll
    for (int i = 0; i < 8; ++i)
#pragma unroll
        for (int j = 0; j < 8; ++j) acc[i][j] = 0.f;

    const int npass = (A2 != nullptr) ? 2 : 1;
    for (int pass = 0; pass < npass; ++pass) {
        const float* __restrict__ A = pass ? A2 : A1;
        const float* __restrict__ B = pass ? B2 : B1;
        for (int k0 = 0; k0 < K; k0 += BK) {
            // A tile load: thread (kk=tx, row=ty+16*r)
#pragma unroll
            for (int r = 0; r < 8; ++r) {
                int row = ty + r * 16;
                float v = 0.f;
                if (m0 + row < M) v = A[(size_t)(m0 + row) * lda + k0 + tx];
                As[tx][row] = v;
            }
            // B tile load: thread (j=tid%128, kk=tid/128 + 2*r)
            {
                int bj = tid & 127;
                int bk0 = tid >> 7;
#pragma unroll
                for (int r = 0; r < 8; ++r) {
                    int kk = bk0 + r * 2;
                    float v = 0.f;
                    if (n0 + bj < N) v = B[(size_t)(k0 + kk) * ldb + n0 + bj];
                    Bs[kk][bj] = v;
                }
            }
            __syncthreads();
#pragma unroll
            for (int kk = 0; kk < BK; ++kk) {
                float a[8], b[8];
                float4 a0 = *(const float4*)&As[kk][ty * 8];
                float4 a1 = *(const float4*)&As[kk][ty * 8 + 4];
                float4 b0 = *(const float4*)&Bs[kk][tx * 8];
                float4 b1 = *(const float4*)&Bs[kk][tx * 8 + 4];
                a[0]=a0.x;a[1]=a0.y;a[2]=a0.z;a[3]=a0.w;a[4]=a1.x;a[5]=a1.y;a[6]=a1.z;a[7]=a1.w;
                b[0]=b0.x;b[1]=b0.y;b[2]=b0.z;b[3]=b0.w;b[4]=b1.x;b[5]=b1.y;b[6]=b1.z;b[7]=b1.w;
#pragma unroll
                for (int i = 0; i < 8; ++i)
#pragma unroll
                    for (int j = 0; j < 8; ++j)
                        acc[i][j] = fmaf(a[i], b[j], acc[i][j]);
            }
            __syncthreads();
        }
    }
    // epilogue
#pragma unroll
    for (int i = 0; i < 8; ++i) {
        int m = m0 + ty * 8 + i;
        if (m >= M) continue;
#pragma unroll
        for (int j = 0; j < 8; ++j) {
            int n = n0 + tx * 8 + j;
            if (n < N) {
                float v = acc[i][j];
                if (bias) v += bias[n];
                C[(size_t)m * ldc + n] = v;
            }
        }
    }
}

// ---------------- fused attention: block per batch row ------------------------
// e[t] = sum_h tanh(Hproj[b,t,h] + q[b,h]) * Ws[h]; alpha = softmax_t(e);
// ctx[b,c] = sum_t alpha[t] * batch_H[b,t,c]
__global__ __launch_bounds__(256)
void attn_kernel(const float* __restrict__ q,
                 const float* __restrict__ batch_H,
                 const float* __restrict__ Ws,
                 float* __restrict__ ctx)
{
    const int b = blockIdx.x;
    __shared__ float qs[HH];
    __shared__ float ws[HH];
    __shared__ float e[TT];

    const int tid = threadIdx.x;
    for (int i = tid; i < HH; i += 256) { qs[i] = q[(size_t)b * HH + i]; ws[i] = Ws[i]; }
    __syncthreads();

    const int warp = tid >> 5, lane = tid & 31;
    // 8 warps, 8 encoder steps each
    for (int t = warp; t < TT; t += 8) {
        const float* __restrict__ hp = g_Hproj + ((size_t)b * TT + t) * HH;
        float p = 0.f;
#pragma unroll 4
        for (int h = lane; h < HH; h += 32)
            p += tanhf(hp[h] + qs[h]) * ws[h];
#pragma unroll
        for (int o = 16; o; o >>= 1) p += __shfl_xor_sync(0xffffffffu, p, o);
        if (lane == 0) e[t] = p;
    }
    __syncthreads();

    // softmax over 64 with warp 0 (2 elems/lane)
    if (warp == 0) {
        float v0 = e[lane], v1 = e[lane + 32];
        float m = fmaxf(v0, v1);
#pragma unroll
        for (int o = 16; o; o >>= 1) m = fmaxf(m, __shfl_xor_sync(0xffffffffu, m, o));
        float x0 = __expf(v0 - m), x1 = __expf(v1 - m);
        float s = x0 + x1;
#pragma unroll
        for (int o = 16; o; o >>= 1) s += __shfl_xor_sync(0xffffffffu, s, o);
        float inv = 1.f / s;
        e[lane] = x0 * inv;
        e[lane + 32] = x1 * inv;
    }
    __syncthreads();

    // context
    for (int c = tid; c < CC; c += 256) {
        const float* __restrict__ bh = batch_H + (size_t)b * TT * CC + c;
        float acc = 0.f;
#pragma unroll 8
        for (int t = 0; t < TT; ++t)
            acc = fmaf(e[t], bh[(size_t)t * CC], acc);
        ctx[(size_t)b * CC + c] = acc;
    }
}

// ---------------- LSTM gates + one-hot row add + bias -------------------------
__device__ __forceinline__ float sigm(float x) { return 1.f / (1.f + __expf(-x)); }

__global__ __launch_bounds__(256)
void gates_kernel(const float* __restrict__ lk,     // lstm_kernel [608,2048]
                  const float* __restrict__ lb,     // lstm_bias [2048]
                  const int* __restrict__ text,     // [B, 26]
                  int step)
{
    int idx = blockIdx.x * 256 + threadIdx.x;       // over B*H
    if (idx >= BB * HH) return;
    const int b = idx >> 9;
    const int j = idx & (HH - 1);
    const int ch = text[b * NS + step];
    const float* __restrict__ row = lk + (size_t)(CC + ch) * (4 * HH);
    const float* __restrict__ zrow = g_z + (size_t)b * (4 * HH);

    float zi = zrow[j]            + row[j]            + lb[j];
    float zf = zrow[HH + j]       + row[HH + j]       + lb[HH + j];
    float zg = zrow[2 * HH + j]   + row[2 * HH + j]   + lb[2 * HH + j];
    float zo = zrow[3 * HH + j]   + row[3 * HH + j]   + lb[3 * HH + j];

    float cn = sigm(zf) * g_c[idx] + sigm(zi) * tanhf(zg);
    float hn = sigm(zo) * tanhf(cn);
    g_c[idx] = cn;
    g_h[idx] = hn;
    g_hs[((size_t)b * NS + step) * HH + j] = hn;
}

// ---------------- launch -------------------------------------------------------
extern "C" void kernel_launch(void* const* d_in, const int* in_sizes, int n_in,
                              void* d_out, int out_size)
{
    // input layout (per reference signature); batch_max_length may or may not be
    // materialized as a scalar input -> detect via size==1 at index 2.
    int off = 0;
    if (n_in >= 3 && in_sizes[2] == 1) off = 1;
    const float* batch_H = (const float*)d_in[0];
    const int*   text    = (const int*)  d_in[1];
    const float* Wi      = (const float*)d_in[2 + off];
    const float* Wh      = (const float*)d_in[3 + off];
    const float* bh      = (const float*)d_in[4 + off];
    const float* Ws      = (const float*)d_in[5 + off];
    const float* lk      = (const float*)d_in[6 + off];
    const float* lr      = (const float*)d_in[7 + off];
    const float* lb      = (const float*)d_in[8 + off];
    const float* Wgen    = (const float*)d_in[9 + off];
    const float* bgen    = (const float*)d_in[10 + off];

    float *Hproj, *q, *ctx, *z, *h, *c, *hs;
    cudaGetSymbolAddress((void**)&Hproj, g_Hproj);
    cudaGetSymbolAddress((void**)&q,     g_q);
    cudaGetSymbolAddress((void**)&ctx,   g_ctx);
    cudaGetSymbolAddress((void**)&z,     g_z);
    cudaGetSymbolAddress((void**)&h,     g_h);
    cudaGetSymbolAddress((void**)&c,     g_c);
    cudaGetSymbolAddress((void**)&hs,    g_hs);

    cudaMemsetAsync(h, 0, (size_t)BB * HH * sizeof(float));
    cudaMemsetAsync(c, 0, (size_t)BB * HH * sizeof(float));

    // Hproj = batch_H(view [B*T, C]) @ Wi    -> [B*T, H]
    gemm_dual<<<dim3(HH / BN, (BB * TT) / BM), 256>>>(
        batch_H, Wi, nullptr, nullptr, nullptr, Hproj,
        BB * TT, HH, CC, CC, HH, HH);

    for (int s = 0; s < NS; ++s) {
        // q = h @ Wh + bh
        gemm_dual<<<dim3(HH / BN, BB / BM), 256>>>(
            h, Wh, nullptr, nullptr, bh, q,
            BB, HH, HH, HH, HH, HH);
        // attention -> ctx
        attn_kernel<<<BB, 256>>>(q, batch_H, Ws, ctx);
        // z = ctx @ lstm_kernel[0:512] + h @ lstm_rec   (bias+onehot in gates)
        gemm_dual<<<dim3((4 * HH) / BN, BB / BM), 256>>>(
            ctx, lk, h, lr, nullptr, z,
            BB, 4 * HH, CC, CC, 4 * HH, 4 * HH);
        // gates: z + lstm_kernel[512+char] + bias -> h,c ; record hs
        gates_kernel<<<(BB * HH) / 256, 256>>>(lk, lb, text, s);
    }

    // probs = hs(view [B*NS, H]) @ Wgen + bgen -> d_out [B*NS, NC]
    gemm_dual<<<dim3(1, (BB * NS) / BM), 256>>>(
        hs, Wgen, nullptr, nullptr, bgen, (float*)d_out,
        BB * NS, NC, HH, HH, NC, NC);
}

// round 4
// speedup vs baseline: 2.9544x; 2.9544x over previous
#include <cuda_runtime.h>
#include <cuda_bf16.h>
#include <cstdint>

// Problem constants
#define BB   512
#define TT   64
#define CC   512
#define HH   512
#define NCLS 96
#define NS   26

// ---------------- device scratch -------------------------------------------
__device__ float g_Hproj[(size_t)BB * TT * HH];
__device__ float g_q   [(size_t)BB * HH];
__device__ float g_ctx [(size_t)BB * HH];
__device__ float g_z   [(size_t)BB * 4 * HH];
__device__ float g_h   [(size_t)BB * HH];
__device__ float g_c   [(size_t)BB * HH];
__device__ float g_hs  [(size_t)BB * NS * HH];

// ---------------- tf32 helpers ----------------------------------------------
__device__ __forceinline__ float to_tf32(float x) {
    uint32_t r;
    asm("cvt.rna.tf32.f32 %0, %1;" : "=r"(r) : "f"(x));
    return __uint_as_float(r);
}

__device__ __forceinline__ void mma_tf32(float* d, const uint32_t* a, const uint32_t* b) {
    asm volatile(
        "mma.sync.aligned.m16n8k8.row.col.f32.tf32.tf32.f32 "
        "{%0,%1,%2,%3}, {%4,%5,%6,%7}, {%8,%9}, {%0,%1,%2,%3};"
        : "+f"(d[0]), "+f"(d[1]), "+f"(d[2]), "+f"(d[3])
        : "r"(a[0]), "r"(a[1]), "r"(a[2]), "r"(a[3]),
          "r"(b[0]), "r"(b[1]));
}

// ---------------- warp-MMA tf32 GEMM: C = A1@B1 (+A2@B2) (+bias) ------------
// Block tile 64x64, BK=16, 128 threads (4 warps of 32x32), ping-pong smem.
#define BM 64
#define BN 64
#define BK 16
#define PAD 4
#define PITCH (BM + PAD)   // also BN + PAD (both 64)

__global__ __launch_bounds__(128)
void gemm_mma(const float* __restrict__ A1, const float* __restrict__ B1,
              const float* __restrict__ A2, const float* __restrict__ B2,
              const float* __restrict__ bias, float* __restrict__ C,
              int M, int N, int K, int lda, int ldb, int ldc)
{
    __shared__ float As[2][BK][PITCH];   // As[k][m]
    __shared__ float Bs[2][BK][PITCH];   // Bs[k][n]

    const int tid = threadIdx.x;
    const int wid = tid >> 5, lane = tid & 31;
    const int warpM = wid >> 1, warpN = wid & 1;     // 2x2 warp grid
    const int g = lane >> 2, t = lane & 3;
    const int m0 = blockIdx.y * BM, n0 = blockIdx.x * BN;

    const int kpt = K / BK;                          // k-tiles per pass
    const int npass = (A2 != nullptr) ? 2 : 1;
    const int nk = kpt * npass;

    float acc[2][4][4];
#pragma unroll
    for (int i = 0; i < 2; ++i)
#pragma unroll
        for (int j = 0; j < 4; ++j)
#pragma unroll
            for (int k = 0; k < 4; ++k) acc[i][j][k] = 0.f;

    // ---- global tile fetch helpers (2 float4 each for A and B per thread) ----
    // A: 64 rows x 4 float4 (BK=16) ; B: 16 rows x 16 float4 (BN=64)
    auto fetch = [&](int kt, float4* rA, float4* rB) {
        const int pass = kt / kpt;
        const int k0 = (kt - pass * kpt) * BK;
        const float* __restrict__ A = pass ? A2 : A1;
        const float* __restrict__ B = pass ? B2 : B1;
#pragma unroll
        for (int j = 0; j < 2; ++j) {
            int l = tid + 128 * j;
            int row = l >> 2, q = l & 3;            // A[m0+row][k0+q*4 ..]
            rA[j] = make_float4(0.f, 0.f, 0.f, 0.f);
            if (m0 + row < M)
                rA[j] = *(const float4*)(A + (size_t)(m0 + row) * lda + k0 + q * 4);
        }
#pragma unroll
        for (int j = 0; j < 2; ++j) {
            int l = tid + 128 * j;
            int kr = l >> 4, q = l & 15;            // B[k0+kr][n0+q*4 ..]
            float4 v = make_float4(0.f, 0.f, 0.f, 0.f);
            int n = n0 + q * 4;
            if (n + 3 < N) {
                v = *(const float4*)(B + (size_t)(k0 + kr) * ldb + n);
            } else {
                const float* src = B + (size_t)(k0 + kr) * ldb;
                float* vf = (float*)&v;
#pragma unroll
                for (int e = 0; e < 4; ++e)
                    if (n + e < N) vf[e] = src[n + e];
            }
            rB[j] = v;
        }
    };
    auto stage = [&](const float4* rA, const float4* rB, int buf) {
#pragma unroll
        for (int j = 0; j < 2; ++j) {
            int l = tid + 128 * j;
            int row = l >> 2, q = l & 3;
            const float* vf = (const float*)&rA[j];
#pragma unroll
            for (int e = 0; e < 4; ++e)
                As[buf][q * 4 + e][row] = to_tf32(vf[e]);
        }
#pragma unroll
        for (int j = 0; j < 2; ++j) {
            int l = tid + 128 * j;
            int kr = l >> 4, q = l & 15;
            const float* vf = (const float*)&rB[j];
            float4 o;
            o.x = to_tf32(vf[0]); o.y = to_tf32(vf[1]);
            o.z = to_tf32(vf[2]); o.w = to_tf32(vf[3]);
            *(float4*)&Bs[buf][kr][q * 4] = o;
        }
    };

    {   // prologue: stage k-tile 0 into buffer 0
        float4 rA[2], rB[2];
        fetch(0, rA, rB);
        stage(rA, rB, 0);
    }
    __syncthreads();

    for (int kt = 0; kt < nk; ++kt) {
        const int buf = kt & 1;
        const bool more = (kt + 1 < nk);
        float4 rA[2], rB[2];
        if (more) fetch(kt + 1, rA, rB);

        // compute on As[buf]/Bs[buf]: two k-steps of 8
#pragma unroll
        for (int ks = 0; ks < 2; ++ks) {
            const int kb = ks * 8;
            uint32_t a[2][4];
#pragma unroll
            for (int mt = 0; mt < 2; ++mt) {
                const int mr = warpM * 32 + mt * 16;
                a[mt][0] = __float_as_uint(As[buf][kb + t    ][mr + g]);
                a[mt][1] = __float_as_uint(As[buf][kb + t    ][mr + g + 8]);
                a[mt][2] = __float_as_uint(As[buf][kb + t + 4][mr + g]);
                a[mt][3] = __float_as_uint(As[buf][kb + t + 4][mr + g + 8]);
            }
            uint32_t b[4][2];
#pragma unroll
            for (int nt = 0; nt < 4; ++nt) {
                const int nc = warpN * 32 + nt * 8 + g;
                b[nt][0] = __float_as_uint(Bs[buf][kb + t    ][nc]);
                b[nt][1] = __float_as_uint(Bs[buf][kb + t + 4][nc]);
            }
#pragma unroll
            for (int mt = 0; mt < 2; ++mt)
#pragma unroll
                for (int nt = 0; nt < 4; ++nt)
                    mma_tf32(acc[mt][nt], a[mt], b[nt]);
        }

        if (more) stage(rA, rB, buf ^ 1);
        __syncthreads();
    }

    // ---- epilogue ----
#pragma unroll
    for (int mt = 0; mt < 2; ++mt) {
#pragma unroll
        for (int nt = 0; nt < 4; ++nt) {
            const int col = n0 + warpN * 32 + nt * 8 + 2 * t;
            const int row = m0 + warpM * 32 + mt * 16 + g;
            float b0 = 0.f, b1 = 0.f;
            if (bias && col + 1 < N) { b0 = bias[col]; b1 = bias[col + 1]; }
            else if (bias && col < N) { b0 = bias[col]; }
            if (col + 1 < N) {
                if (row < M) {
                    float2 v = make_float2(acc[mt][nt][0] + b0, acc[mt][nt][1] + b1);
                    *(float2*)(C + (size_t)row * ldc + col) = v;
                }
                if (row + 8 < M) {
                    float2 v = make_float2(acc[mt][nt][2] + b0, acc[mt][nt][3] + b1);
                    *(float2*)(C + (size_t)(row + 8) * ldc + col) = v;
                }
            } else if (col < N) {
                if (row < M)     C[(size_t)row * ldc + col]       = acc[mt][nt][0] + b0;
                if (row + 8 < M) C[(size_t)(row + 8) * ldc + col] = acc[mt][nt][2] + b0;
            }
        }
    }
}

// ---------------- fused attention --------------------------------------------
__global__ __launch_bounds__(256)
void attn_kernel(const float* __restrict__ q,
                 const float* __restrict__ batch_H,
                 const float* __restrict__ Ws,
                 float* __restrict__ ctx)
{
    const int b = blockIdx.x;
    __shared__ float qs[HH];
    __shared__ float ws[HH];
    __shared__ float e[TT];

    const int tid = threadIdx.x;
    for (int i = tid; i < HH; i += 256) { qs[i] = q[(size_t)b * HH + i]; ws[i] = Ws[i]; }
    __syncthreads();

    const int warp = tid >> 5, lane = tid & 31;
    for (int t = warp; t < TT; t += 8) {
        const float* __restrict__ hp = g_Hproj + ((size_t)b * TT + t) * HH;
        float p = 0.f;
#pragma unroll 4
        for (int h = lane; h < HH; h += 32)
            p += tanhf(hp[h] + qs[h]) * ws[h];
#pragma unroll
        for (int o = 16; o; o >>= 1) p += __shfl_xor_sync(0xffffffffu, p, o);
        if (lane == 0) e[t] = p;
    }
    __syncthreads();

    if (warp == 0) {
        float v0 = e[lane], v1 = e[lane + 32];
        float m = fmaxf(v0, v1);
#pragma unroll
        for (int o = 16; o; o >>= 1) m = fmaxf(m, __shfl_xor_sync(0xffffffffu, m, o));
        float x0 = __expf(v0 - m), x1 = __expf(v1 - m);
        float s = x0 + x1;
#pragma unroll
        for (int o = 16; o; o >>= 1) s += __shfl_xor_sync(0xffffffffu, s, o);
        float inv = 1.f / s;
        e[lane] = x0 * inv;
        e[lane + 32] = x1 * inv;
    }
    __syncthreads();

    for (int c = tid; c < CC; c += 256) {
        const float* __restrict__ bhp = batch_H + (size_t)b * TT * CC + c;
        float acc = 0.f;
#pragma unroll 8
        for (int t = 0; t < TT; ++t)
            acc = fmaf(e[t], bhp[(size_t)t * CC], acc);
        ctx[(size_t)b * CC + c] = acc;
    }
}

// ---------------- LSTM gates -------------------------------------------------
__device__ __forceinline__ float sigm(float x) { return 1.f / (1.f + __expf(-x)); }

__global__ __launch_bounds__(256)
void gates_kernel(const float* __restrict__ lk,
                  const float* __restrict__ lb,
                  const int* __restrict__ text,
                  int step)
{
    int idx = blockIdx.x * 256 + threadIdx.x;
    if (idx >= BB * HH) return;
    const int b = idx >> 9;
    const int j = idx & (HH - 1);
    const int ch = text[b * NS + step];
    const float* __restrict__ row = lk + (size_t)(CC + ch) * (4 * HH);
    const float* __restrict__ zrow = g_z + (size_t)b * (4 * HH);

    float zi = zrow[j]          + row[j]          + lb[j];
    float zf = zrow[HH + j]     + row[HH + j]     + lb[HH + j];
    float zg = zrow[2*HH + j]   + row[2*HH + j]   + lb[2*HH + j];
    float zo = zrow[3*HH + j]   + row[3*HH + j]   + lb[3*HH + j];

    float cn = sigm(zf) * g_c[idx] + sigm(zi) * tanhf(zg);
    float hn = sigm(zo) * tanhf(cn);
    g_c[idx] = cn;
    g_h[idx] = hn;
    g_hs[((size_t)b * NS + step) * HH + j] = hn;
}

// ---------------- launch -----------------------------------------------------
extern "C" void kernel_launch(void* const* d_in, const int* in_sizes, int n_in,
                              void* d_out, int out_size)
{
    int off = 0;
    if (n_in >= 3 && in_sizes[2] == 1) off = 1;
    const float* batch_H = (const float*)d_in[0];
    const int*   text    = (const int*)  d_in[1];
    const float* Wi      = (const float*)d_in[2 + off];
    const float* Wh      = (const float*)d_in[3 + off];
    const float* bh      = (const float*)d_in[4 + off];
    const float* Ws      = (const float*)d_in[5 + off];
    const float* lk      = (const float*)d_in[6 + off];
    const float* lr      = (const float*)d_in[7 + off];
    const float* lb      = (const float*)d_in[8 + off];
    const float* Wgen    = (const float*)d_in[9 + off];
    const float* bgen    = (const float*)d_in[10 + off];

    float *Hproj, *q, *ctx, *z, *h, *c, *hs;
    cudaGetSymbolAddress((void**)&Hproj, g_Hproj);
    cudaGetSymbolAddress((void**)&q,     g_q);
    cudaGetSymbolAddress((void**)&ctx,   g_ctx);
    cudaGetSymbolAddress((void**)&z,     g_z);
    cudaGetSymbolAddress((void**)&h,     g_h);
    cudaGetSymbolAddress((void**)&c,     g_c);
    cudaGetSymbolAddress((void**)&hs,    g_hs);

    cudaMemsetAsync(h, 0, (size_t)BB * HH * sizeof(float));
    cudaMemsetAsync(c, 0, (size_t)BB * HH * sizeof(float));

    // Hproj = batch_H [B*T, C] @ Wi [C, H]
    gemm_mma<<<dim3(HH / BN, (BB * TT) / BM), 128>>>(
        batch_H, Wi, nullptr, nullptr, nullptr, Hproj,
        BB * TT, HH, CC, CC, HH, HH);

    for (int s = 0; s < NS; ++s) {
        // q = h @ Wh + bh
        gemm_mma<<<dim3(HH / BN, BB / BM), 128>>>(
            h, Wh, nullptr, nullptr, bh, q,
            BB, HH, HH, HH, HH, HH);
        attn_kernel<<<BB, 256>>>(q, batch_H, Ws, ctx);
        // z = ctx @ lk[0:512] + h @ lr
        gemm_mma<<<dim3((4 * HH) / BN, BB / BM), 128>>>(
            ctx, lk, h, lr, nullptr, z,
            BB, 4 * HH, CC, CC, 4 * HH, 4 * HH);
        gates_kernel<<<(BB * HH) / 256, 256>>>(lk, lb, text, s);
    }

    // probs = hs [B*NS, H] @ Wgen [H, NC] + bgen
    gemm_mma<<<dim3((NCLS + BN - 1) / BN, (BB * NS) / BM), 128>>>(
        hs, Wgen, nullptr, nullptr, bgen, (float*)d_out,
        BB * NS, NCLS, HH, HH, NCLS, NCLS);
}